// round 6
// baseline (speedup 1.0000x reference)
#include <cuda_runtime.h>

typedef unsigned long long ull;

constexpr int cN = 256, cC = 64, cT = 128, cV = 25, cO = 64;
constexpr int TT  = 8;          // t-chunk per block in k_main
constexpr int TU  = TT * cV;    // 200 (t,u) entries per chunk
constexpr int OG  = 16;         // output channels per group
constexpr int NOG = cO / OG;    // 4
constexpr int PAD = cV + 1;     // 26, even row length for f32x2 over u

// scratch (no allocations allowed)
__device__ float g_xsum[cN * cC * cV];                    // 1.6 MB
__device__ float g_att[(size_t)cN * cO * cV * cV];        // 41 MB

// ---------------------------------------------------------------------------
// K1: xsum[n,c,v] = sum_t x[n,c,t,v]
// grid (8, N), 256 threads: warp w handles c = bx*8+w, lanes 0..24 handle v.
// Consecutive t iterations cover contiguous memory -> near-full sector use.
// ---------------------------------------------------------------------------
__global__ void k_sum_t(const float* __restrict__ x) {
    int n = blockIdx.y;
    int c = blockIdx.x * 8 + (threadIdx.x >> 5);
    int lane = threadIdx.x & 31;
    if (lane < cV) {
        const float* p = x + ((size_t)(n * cC + c) * cT) * cV + lane;
        float s = 0.f;
        #pragma unroll 8
        for (int t = 0; t < cT; ++t) s += p[t * cV];
        g_xsum[(n * cC + c) * cV + lane] = s;
    }
}

// ---------------------------------------------------------------------------
// K2: per-n block: k,q -> conv1/conv2 -> tanh -> ffn -> alpha*att + adj
// writes g_att[n,o,v,u]. grid (N), 256 threads.
// ---------------------------------------------------------------------------
__global__ void k_att_kernel(
    const float* __restrict__ adj,
    const float* __restrict__ Wk, const float* __restrict__ bk,
    const float* __restrict__ Wq, const float* __restrict__ bq,
    const float* __restrict__ c1w, const float* __restrict__ c1b,
    const float* __restrict__ c2w, const float* __restrict__ c2b,
    const float* __restrict__ fw,  const float* __restrict__ fb,
    const float* __restrict__ alpha) {
    __shared__ float xs2[cC * cV];        // 1600
    __shared__ float ksh[4 * cV], qsh[4 * cV];
    __shared__ float fwsh[cO * 8];
    __shared__ float adjsh[cV * cV];
    __shared__ float c1sh[16], c2sh[16], c1bs[4], c2bs[4], fbs[cO], bks[4], bqs[4];

    int n = blockIdx.x, tid = threadIdx.x;
    for (int i = tid; i < cC * cV; i += blockDim.x) xs2[i] = g_xsum[n * cC * cV + i];
    for (int i = tid; i < cO * 8; i += blockDim.x)  fwsh[i] = fw[i];
    for (int i = tid; i < cV * cV; i += blockDim.x) adjsh[i] = adj[i];
    if (tid < 16) { c1sh[tid] = c1w[tid]; c2sh[tid] = c2w[tid]; }
    if (tid < 4)  { c1bs[tid] = c1b[tid]; c2bs[tid] = c2b[tid]; bks[tid] = bk[tid]; bqs[tid] = bq[tid]; }
    if (tid < cO) fbs[tid] = fb[tid];
    __syncthreads();

    if (tid < 100) {                        // k[r,v]
        int r = tid / cV, v = tid % cV;
        float a = 0.f;
        for (int c = 0; c < cC; ++c) a += Wk[r * cC + c] * xs2[c * cV + v];
        ksh[tid] = a * (1.f / cT) + bks[r];
    } else if (tid < 200) {                 // q[r,v]
        int j = tid - 100;
        int r = j / cV, v = j % cV;
        float a = 0.f;
        for (int c = 0; c < cC; ++c) a += Wq[r * cC + c] * xs2[c * cV + v];
        qsh[j] = a * (1.f / cT) + bqs[r];
    }
    __syncthreads();

    float al = alpha[0];
    for (int p = tid; p < cV * cV; p += blockDim.x) {
        int v = p / cV, u = p - v * cV;
        float kv[4], qu[4], aarr[8];
        #pragma unroll
        for (int r = 0; r < 4; ++r) { kv[r] = ksh[r * cV + v]; qu[r] = qsh[r * cV + u]; }
        #pragma unroll
        for (int s = 0; s < 4; ++s) {
            float s1 = c1bs[s], s2 = c2bs[s];
            #pragma unroll
            for (int r = 0; r < 4; ++r) {
                s1 += c1sh[s * 4 + r] * (kv[r] * qu[r]);
                s2 += c2sh[s * 4 + r] * (kv[r] - qu[r]);
            }
            aarr[s]     = tanhf(s1);
            aarr[4 + s] = tanhf(s2);
        }
        float ad = adjsh[p];
        size_t base = (size_t)n * cO * (cV * cV) + p;
        #pragma unroll 8
        for (int o = 0; o < cO; ++o) {
            float acc = fbs[o];
            #pragma unroll
            for (int j = 0; j < 8; ++j) acc += fwsh[o * 8 + j] * aarr[j];
            g_att[base + (size_t)o * (cV * cV)] = al * acc + ad;
        }
    }
}

// ---------------------------------------------------------------------------
// K3: fused vten GEMM + att matmul, f32x2 packed math.
// grid (T/TT, N), 256 threads, dynamic smem.
// SMEM layout (floats):
//   xs   [C][TU]          @ 0       (12800)
//   vt   [OG][TT*PAD]     @ 12800   (3328)   u=25 column is zero pad
//   at   [OG][V*PAD]      @ 16128   (10400)  u=25 column is zero pad
//   wv2  [OG/2][C] float2 @ 26528   (1024)   duplicated o-pairs
//   bvs  [O]              @ 27552   (64)
// total 27616 floats = 110464 B -> 2 blocks/SM
// ---------------------------------------------------------------------------
constexpr int SM_VT = cC * TU;                       // 12800
constexpr int SM_AT = SM_VT + OG * TT * PAD;         // 16128
constexpr int SM_WV = SM_AT + OG * cV * PAD;         // 26528
constexpr int SM_BV = SM_WV + (OG / 2) * cC * 2;     // 27552
constexpr int SM_TOT = SM_BV + cO;                   // 27616

__global__ void __launch_bounds__(256) k_main(
    const float* __restrict__ x, const float* __restrict__ Wv,
    const float* __restrict__ bv, float* __restrict__ out) {
    extern __shared__ float sm[];
    float*  xs  = sm;
    float*  vt  = sm + SM_VT;
    float*  at  = sm + SM_AT;
    float2* wv2 = (float2*)(sm + SM_WV);
    float*  bvs = sm + SM_BV;

    int n  = blockIdx.y;
    int t0 = blockIdx.x * TT;
    int tid = threadIdx.x;

    // stage x tile: per c a contiguous run of TU floats (16B aligned)
    for (int i = tid; i < cC * (TU / 4); i += 256) {
        int c = i / (TU / 4), j = i - c * (TU / 4);
        ((float4*)xs)[i] =
            ((const float4*)(x + ((size_t)(n * cC + c) * cT + t0) * cV))[j];
    }
    if (tid < cO) bvs[tid] = bv[tid];
    if (tid < OG * TT) {                      // zero the u=25 pad of vt once
        int oi = tid / TT, t = tid - oi * TT;
        vt[oi * (TT * PAD) + t * PAD + cV] = 0.f;
    }
    int tloc = tid / cV;
    int uloc = tid - tloc * cV;               // u in phase1, v in phase2

    for (int og = 0; og < NOG; ++og) {
        int o0 = og * OG;
        __syncthreads();   // prior phase2 done before overwriting at/wv2/vt

        for (int i = tid; i < (OG / 2) * cC; i += 256) {
            int pp = i >> 6, c = i & 63;
            wv2[i] = make_float2(Wv[(o0 + 2 * pp) * cC + c],
                                 Wv[(o0 + 2 * pp + 1) * cC + c]);
        }
        for (int i = tid; i < OG * cV * PAD; i += 256) {
            int oi = i / (cV * PAD);
            int j  = i - oi * (cV * PAD);
            int v  = j / PAD, u = j - v * PAD;
            at[i] = (u < cV)
                ? g_att[(((size_t)n * cO + o0 + oi) * cV + v) * cV + u]
                : 0.f;
        }
        __syncthreads();

        // phase 1: vten[o, t, u] = sum_c Wv[o,c] * x[n,c,t0+t,u] + bv[o]
        if (tid < TU) {
            ull acc[OG / 2];
            #pragma unroll
            for (int pp = 0; pp < OG / 2; ++pp) acc[pp] = 0ull;
            #pragma unroll 4
            for (int c = 0; c < cC; ++c) {
                float xv = xs[c * TU + tid];
                ull xv2;
                asm("mov.b64 %0, {%1, %1};" : "=l"(xv2) : "f"(xv));
                #pragma unroll
                for (int pp = 0; pp < OG / 2; ++pp) {
                    ull w = *reinterpret_cast<const ull*>(&wv2[pp * cC + c]);
                    asm("fma.rn.f32x2 %0, %1, %2, %0;"
                        : "+l"(acc[pp]) : "l"(xv2), "l"(w));
                }
            }
            int row = tloc * PAD + uloc;
            #pragma unroll
            for (int pp = 0; pp < OG / 2; ++pp) {
                float lo, hi;
                asm("mov.b64 {%0, %1}, %2;" : "=f"(lo), "=f"(hi) : "l"(acc[pp]));
                vt[(2 * pp)     * (TT * PAD) + row] = lo + bvs[o0 + 2 * pp];
                vt[(2 * pp + 1) * (TT * PAD) + row] = hi + bvs[o0 + 2 * pp + 1];
            }
        }
        __syncthreads();

        // phase 2: out[n,o,t0+t,v] = sum_u att[o,v,u] * vten[o,t,u]
        if (tid < TU) {
            size_t obase = (((size_t)n * cO + o0) * cT + (t0 + tloc)) * cV + uloc;
            #pragma unroll
            for (int oi = 0; oi < OG; ++oi) {
                const ull* arow =
                    reinterpret_cast<const ull*>(at + oi * (cV * PAD) + uloc * PAD);
                const ull* vrow =
                    reinterpret_cast<const ull*>(vt + oi * (TT * PAD) + tloc * PAD);
                ull acc = 0ull;
                #pragma unroll
                for (int up = 0; up < PAD / 2; ++up) {
                    asm("fma.rn.f32x2 %0, %1, %2, %0;"
                        : "+l"(acc) : "l"(arow[up]), "l"(vrow[up]));
                }
                float lo, hi;
                asm("mov.b64 {%0, %1}, %2;" : "=f"(lo), "=f"(hi) : "l"(acc));
                out[obase + (size_t)oi * cT * cV] = lo + hi;
            }
        }
    }
}

// ---------------------------------------------------------------------------
extern "C" void kernel_launch(void* const* d_in, const int* in_sizes, int n_in,
                              void* d_out, int out_size) {
    const float* x    = (const float*)d_in[0];
    const float* adj  = (const float*)d_in[1];
    const float* Wk   = (const float*)d_in[2];
    const float* bk   = (const float*)d_in[3];
    const float* Wq   = (const float*)d_in[4];
    const float* bq   = (const float*)d_in[5];
    const float* Wv   = (const float*)d_in[6];
    const float* bv   = (const float*)d_in[7];
    const float* c1w  = (const float*)d_in[8];
    const float* c1b  = (const float*)d_in[9];
    const float* c2w  = (const float*)d_in[10];
    const float* c2b  = (const float*)d_in[11];
    const float* fw   = (const float*)d_in[12];
    const float* fb   = (const float*)d_in[13];
    const float* alpha= (const float*)d_in[14];
    float* out = (float*)d_out;

    cudaFuncSetAttribute((const void*)k_main,
                         cudaFuncAttributeMaxDynamicSharedMemorySize,
                         SM_TOT * (int)sizeof(float));

    k_sum_t<<<dim3(8, cN), 256>>>(x);
    k_att_kernel<<<cN, 256>>>(adj, Wk, bk, Wq, bq, c1w, c1b, c2w, c2b, fw, fb, alpha);
    k_main<<<dim3(cT / TT, cN), 256, SM_TOT * (int)sizeof(float)>>>(x, Wv, bv, out);
}

// round 8
// speedup vs baseline: 1.1769x; 1.1769x over previous
#include <cuda_runtime.h>

typedef unsigned long long ull;

constexpr int cN = 256, cC = 64, cT = 128, cV = 25, cO = 64;
constexpr int TT  = 8;            // t-chunk per block in k_main
constexpr int TU  = TT * cV;      // 200 (t,u) entries per chunk
constexpr int PAD = cV + 1;       // 26: even row length for f32x2 over u

// scratch (no allocations allowed)
__device__ float g_xsum[cN * cC * cV];                    // 1.6 MB
__device__ float g_att[(size_t)cN * cO * cV * cV];        // 41 MB

// ---------------------------------------------------------------------------
// K1: xsum[n,c,v] = sum_t x[n,c,t,v]   (HBM-roof bound, 40us, unchanged)
// ---------------------------------------------------------------------------
__global__ void k_sum_t(const float* __restrict__ x) {
    int n = blockIdx.y;
    int c = blockIdx.x * 8 + (threadIdx.x >> 5);
    int lane = threadIdx.x & 31;
    if (lane < cV) {
        const float* p = x + ((size_t)(n * cC + c) * cT) * cV + lane;
        float s = 0.f;
        #pragma unroll 8
        for (int t = 0; t < cT; ++t) s += p[t * cV];
        g_xsum[(n * cC + c) * cV + lane] = s;
    }
}

// ---------------------------------------------------------------------------
// K2: per-n attention matrix (k,q -> conv -> tanh -> ffn -> alpha*att+adj)
// ---------------------------------------------------------------------------
__global__ void k_att_kernel(
    const float* __restrict__ adj,
    const float* __restrict__ Wk, const float* __restrict__ bk,
    const float* __restrict__ Wq, const float* __restrict__ bq,
    const float* __restrict__ c1w, const float* __restrict__ c1b,
    const float* __restrict__ c2w, const float* __restrict__ c2b,
    const float* __restrict__ fw,  const float* __restrict__ fb,
    const float* __restrict__ alpha) {
    __shared__ float xs2[cC * cV];
    __shared__ float ksh[4 * cV], qsh[4 * cV];
    __shared__ float fwsh[cO * 8];
    __shared__ float adjsh[cV * cV];
    __shared__ float c1sh[16], c2sh[16], c1bs[4], c2bs[4], fbs[cO], bks[4], bqs[4];

    int n = blockIdx.x, tid = threadIdx.x;
    for (int i = tid; i < cC * cV; i += blockDim.x) xs2[i] = g_xsum[n * cC * cV + i];
    for (int i = tid; i < cO * 8; i += blockDim.x)  fwsh[i] = fw[i];
    for (int i = tid; i < cV * cV; i += blockDim.x) adjsh[i] = adj[i];
    if (tid < 16) { c1sh[tid] = c1w[tid]; c2sh[tid] = c2w[tid]; }
    if (tid < 4)  { c1bs[tid] = c1b[tid]; c2bs[tid] = c2b[tid]; bks[tid] = bk[tid]; bqs[tid] = bq[tid]; }
    if (tid < cO) fbs[tid] = fb[tid];
    __syncthreads();

    if (tid < 100) {
        int r = tid / cV, v = tid % cV;
        float a = 0.f;
        for (int c = 0; c < cC; ++c) a += Wk[r * cC + c] * xs2[c * cV + v];
        ksh[tid] = a * (1.f / cT) + bks[r];
    } else if (tid < 200) {
        int j = tid - 100;
        int r = j / cV, v = j % cV;
        float a = 0.f;
        for (int c = 0; c < cC; ++c) a += Wq[r * cC + c] * xs2[c * cV + v];
        qsh[j] = a * (1.f / cT) + bqs[r];
    }
    __syncthreads();

    float al = alpha[0];
    for (int p = tid; p < cV * cV; p += blockDim.x) {
        int v = p / cV, u = p - v * cV;
        float kv[4], qu[4], aarr[8];
        #pragma unroll
        for (int r = 0; r < 4; ++r) { kv[r] = ksh[r * cV + v]; qu[r] = qsh[r * cV + u]; }
        #pragma unroll
        for (int s = 0; s < 4; ++s) {
            float s1 = c1bs[s], s2 = c2bs[s];
            #pragma unroll
            for (int r = 0; r < 4; ++r) {
                s1 += c1sh[s * 4 + r] * (kv[r] * qu[r]);
                s2 += c2sh[s * 4 + r] * (kv[r] - qu[r]);
            }
            aarr[s]     = tanhf(s1);
            aarr[4 + s] = tanhf(s2);
        }
        float ad = adjsh[p];
        size_t base = (size_t)n * cO * (cV * cV) + p;
        #pragma unroll 8
        for (int o = 0; o < cO; ++o) {
            float acc = fbs[o];
            #pragma unroll
            for (int j = 0; j < 8; ++j) acc += fwsh[o * 8 + j] * aarr[j];
            g_att[base + (size_t)o * (cV * cV)] = al * acc + ad;
        }
    }
}

// ---------------------------------------------------------------------------
// K3: fused vten GEMM + att matmul, register-tiled, 512 thr, 1 block/SM.
// SMEM (floats):
//   region A [0, 41600):
//     phase1 view : xs[64][200] @ 0 (12800) ; wv2 ull[32][64] @ 12800 (4096 fl)
//     phase2 view : at[64][v*26+u] (41600)   -- reuses the same space
//   vt[64][TT*26] @ 41600 (13312)
// total 54912 floats = 219648 B  (1 block/SM)
// ---------------------------------------------------------------------------
constexpr int SM_WV  = cC * TU;                 // 12800 (float offset of wv2)
constexpr int SM_VT  = cO * cV * PAD;           // 41600 (float offset of vt)
constexpr int SM_TOT = SM_VT + cO * TT * PAD;   // 54912 floats

__global__ void __launch_bounds__(512) k_main(
    const float* __restrict__ x, const float* __restrict__ Wv,
    const float* __restrict__ bv, float* __restrict__ out) {
    extern __shared__ float sm[];
    float* regA = sm;                 // xs+wv2 in phase1, at in phase2
    float* xs   = sm;
    ull*   wv2u = (ull*)(sm + SM_WV);
    float* vt   = sm + SM_VT;

    int n  = blockIdx.y;
    int t0 = blockIdx.x * TT;
    int tid = threadIdx.x;

    // ---- stage x tile: per c one contiguous run of 200 floats (50 float4) ----
    for (int i = tid; i < cC * (TU / 4); i += 512) {
        int c = i / (TU / 4), j = i - c * (TU / 4);
        ((float4*)xs)[i] =
            ((const float4*)(x + ((size_t)(n * cC + c) * cT + t0) * cV))[j];
    }
    // wv2: duplicated o-pairs, [pp][c] as ull
    for (int i = tid; i < 32 * cC; i += 512) {
        int pp = i >> 6, c = i & 63;
        ((float2*)wv2u)[i] = make_float2(Wv[(2 * pp) * cC + c],
                                         Wv[(2 * pp + 1) * cC + c]);
    }
    {   // zero the u=25 pad column of vt (64 o x 8 t = 512 entries)
        int o = tid >> 3, t = tid & 7;
        vt[o * (TT * PAD) + t * PAD + cV] = 0.f;
    }
    __syncthreads();

    // ---- phase 1: vten[o][t*26+u] = sum_c Wv[o,c]*x[c][tu] + bv[o] ----------
    // thread tile: 8 o (osub) x 4 tu. 8 osub x 50 tu-groups = 400 threads.
    if (tid < 400) {
        int osub = tid / 50, tug = tid - osub * 50;
        int tu0  = tug * 4;
        const ull* wbase = wv2u + (osub * 4) * cC;

        ull acc[4][4];
        #pragma unroll
        for (int pp = 0; pp < 4; ++pp)
            #pragma unroll
            for (int j = 0; j < 4; ++j) acc[pp][j] = 0ull;

        #pragma unroll 4
        for (int c = 0; c < cC; ++c) {
            float4 x4 = *(const float4*)(xs + c * TU + tu0);
            ull xd[4];
            asm("mov.b64 %0, {%1, %1};" : "=l"(xd[0]) : "f"(x4.x));
            asm("mov.b64 %0, {%1, %1};" : "=l"(xd[1]) : "f"(x4.y));
            asm("mov.b64 %0, {%1, %1};" : "=l"(xd[2]) : "f"(x4.z));
            asm("mov.b64 %0, {%1, %1};" : "=l"(xd[3]) : "f"(x4.w));
            #pragma unroll
            for (int pp = 0; pp < 4; ++pp) {
                ull w = wbase[pp * cC + c];
                #pragma unroll
                for (int j = 0; j < 4; ++j)
                    asm("fma.rn.f32x2 %0, %1, %2, %0;"
                        : "+l"(acc[pp][j]) : "l"(xd[j]), "l"(w));
            }
        }
        #pragma unroll
        for (int pp = 0; pp < 4; ++pp) {
            int olo = osub * 8 + 2 * pp;
            float blo = __ldg(bv + olo), bhi = __ldg(bv + olo + 1);
            #pragma unroll
            for (int j = 0; j < 4; ++j) {
                int tu = tu0 + j, t = tu / 25, u = tu - 25 * t;
                float lo, hi;
                asm("mov.b64 {%0, %1}, %2;" : "=f"(lo), "=f"(hi) : "l"(acc[pp][j]));
                vt[olo       * (TT * PAD) + t * PAD + u] = lo + blo;
                vt[(olo + 1) * (TT * PAD) + t * PAD + u] = hi + bhi;
            }
        }
    }
    __syncthreads();

    // ---- load full 64-o att tile over the xs/wv2 region (u padded to 26) ----
    for (int i = tid; i < cO * cV * PAD; i += 512) {
        int o = i / (cV * PAD);
        int j = i - o * (cV * PAD);
        int v = j / PAD, u = j - v * PAD;
        regA[i] = (u < cV)
            ? g_att[(((size_t)n * cO + o) * cV + v) * cV + u]
            : 0.f;
    }
    __syncthreads();

    // ---- phase 2: out[o,t,v] = sum_u at[o][v][u] * vt[o][t][u] --------------
    // thread tile: 1 o x 5 v (interleaved v = vsub + 5*vi) x 4 t (two halves).
    // 64 o x 5 vsub = 320 threads.
    if (tid < 320) {
        int o = tid / 5, vsub = tid - 5 * o;
        const float* arow0 = regA + o * (cV * PAD);
        const float* vrow0 = vt   + o * (TT * PAD);
        size_t ob = (((size_t)n * cO + o) * cT + t0) * cV;

        #pragma unroll
        for (int th = 0; th < 2; ++th) {
            ull acc[5][4];
            #pragma unroll
            for (int vi = 0; vi < 5; ++vi)
                #pragma unroll
                for (int ti = 0; ti < 4; ++ti) acc[vi][ti] = 0ull;

            #pragma unroll
            for (int up = 0; up < PAD / 2; ++up) {
                ull a_u[5], v_u[4];
                #pragma unroll
                for (int vi = 0; vi < 5; ++vi)
                    a_u[vi] = *(const ull*)(arow0 + (vsub + 5 * vi) * PAD + 2 * up);
                #pragma unroll
                for (int ti = 0; ti < 4; ++ti)
                    v_u[ti] = *(const ull*)(vrow0 + (4 * th + ti) * PAD + 2 * up);
                #pragma unroll
                for (int vi = 0; vi < 5; ++vi)
                    #pragma unroll
                    for (int ti = 0; ti < 4; ++ti)
                        asm("fma.rn.f32x2 %0, %1, %2, %0;"
                            : "+l"(acc[vi][ti]) : "l"(a_u[vi]), "l"(v_u[ti]));
            }
            #pragma unroll
            for (int ti = 0; ti < 4; ++ti) {
                int t = 4 * th + ti;
                #pragma unroll
                for (int vi = 0; vi < 5; ++vi) {
                    float lo, hi;
                    asm("mov.b64 {%0, %1}, %2;" : "=f"(lo), "=f"(hi) : "l"(acc[vi][ti]));
                    out[ob + (size_t)t * cV + vsub + 5 * vi] = lo + hi;
                }
            }
        }
    }
}

// ---------------------------------------------------------------------------
extern "C" void kernel_launch(void* const* d_in, const int* in_sizes, int n_in,
                              void* d_out, int out_size) {
    const float* x    = (const float*)d_in[0];
    const float* adj  = (const float*)d_in[1];
    const float* Wk   = (const float*)d_in[2];
    const float* bk   = (const float*)d_in[3];
    const float* Wq   = (const float*)d_in[4];
    const float* bq   = (const float*)d_in[5];
    const float* Wv   = (const float*)d_in[6];
    const float* bv   = (const float*)d_in[7];
    const float* c1w  = (const float*)d_in[8];
    const float* c1b  = (const float*)d_in[9];
    const float* c2w  = (const float*)d_in[10];
    const float* c2b  = (const float*)d_in[11];
    const float* fw   = (const float*)d_in[12];
    const float* fb   = (const float*)d_in[13];
    const float* alpha= (const float*)d_in[14];
    float* out = (float*)d_out;

    cudaFuncSetAttribute((const void*)k_main,
                         cudaFuncAttributeMaxDynamicSharedMemorySize,
                         SM_TOT * (int)sizeof(float));

    k_sum_t<<<dim3(8, cN), 256>>>(x);
    k_att_kernel<<<cN, 256>>>(adj, Wk, bk, Wq, bq, c1w, c1b, c2w, c2b, fw, fb, alpha);
    k_main<<<dim3(cT / TT, cN), 512, SM_TOT * (int)sizeof(float)>>>(x, Wv, bv, out);
}

// round 9
// speedup vs baseline: 1.9220x; 1.6330x over previous
#include <cuda_runtime.h>

typedef unsigned long long ull;

constexpr int cN = 256, cC = 64, cT = 128, cV = 25, cO = 64;
constexpr int TV  = cT * cV;          // 3200 contiguous (t,v) per (n, channel)

// scratch (no allocations allowed)
__device__ float g_xsum[cN * cC * cV];                    // 1.6 MB
__device__ float g_att[(size_t)cN * cO * cV * cV];        // 41 MB
__device__ float g_vten[(size_t)cN * cO * TV];            // 210 MB

// ---------------------------------------------------------------------------
// K1: xsum[n,c,v] = sum_t x[n,c,t,v]   (HBM-roof bound, ~40us)
// ---------------------------------------------------------------------------
__global__ void k_sum_t(const float* __restrict__ x) {
    int n = blockIdx.y;
    int c = blockIdx.x * 8 + (threadIdx.x >> 5);
    int lane = threadIdx.x & 31;
    if (lane < cV) {
        const float* p = x + ((size_t)(n * cC + c) * cT) * cV + lane;
        float s = 0.f;
        #pragma unroll 8
        for (int t = 0; t < cT; ++t) s += p[t * cV];
        g_xsum[(n * cC + c) * cV + lane] = s;
    }
}

// ---------------------------------------------------------------------------
// K2: per-n attention matrix (k,q -> conv -> tanh -> ffn -> alpha*att+adj)
// ---------------------------------------------------------------------------
__global__ void k_att_kernel(
    const float* __restrict__ adj,
    const float* __restrict__ Wk, const float* __restrict__ bk,
    const float* __restrict__ Wq, const float* __restrict__ bq,
    const float* __restrict__ c1w, const float* __restrict__ c1b,
    const float* __restrict__ c2w, const float* __restrict__ c2b,
    const float* __restrict__ fw,  const float* __restrict__ fb,
    const float* __restrict__ alpha) {
    __shared__ float xs2[cC * cV];
    __shared__ float ksh[4 * cV], qsh[4 * cV];
    __shared__ float fwsh[cO * 8];
    __shared__ float adjsh[cV * cV];
    __shared__ float c1sh[16], c2sh[16], c1bs[4], c2bs[4], fbs[cO], bks[4], bqs[4];

    int n = blockIdx.x, tid = threadIdx.x;
    for (int i = tid; i < cC * cV; i += blockDim.x) xs2[i] = g_xsum[n * cC * cV + i];
    for (int i = tid; i < cO * 8; i += blockDim.x)  fwsh[i] = fw[i];
    for (int i = tid; i < cV * cV; i += blockDim.x) adjsh[i] = adj[i];
    if (tid < 16) { c1sh[tid] = c1w[tid]; c2sh[tid] = c2w[tid]; }
    if (tid < 4)  { c1bs[tid] = c1b[tid]; c2bs[tid] = c2b[tid]; bks[tid] = bk[tid]; bqs[tid] = bq[tid]; }
    if (tid < cO) fbs[tid] = fb[tid];
    __syncthreads();

    if (tid < 100) {
        int r = tid / cV, v = tid % cV;
        float a = 0.f;
        for (int c = 0; c < cC; ++c) a += Wk[r * cC + c] * xs2[c * cV + v];
        ksh[tid] = a * (1.f / cT) + bks[r];
    } else if (tid < 200) {
        int j = tid - 100;
        int r = j / cV, v = j % cV;
        float a = 0.f;
        for (int c = 0; c < cC; ++c) a += Wq[r * cC + c] * xs2[c * cV + v];
        qsh[j] = a * (1.f / cT) + bqs[r];
    }
    __syncthreads();

    float al = alpha[0];
    for (int p = tid; p < cV * cV; p += blockDim.x) {
        int v = p / cV, u = p - v * cV;
        float kv[4], qu[4], aarr[8];
        #pragma unroll
        for (int r = 0; r < 4; ++r) { kv[r] = ksh[r * cV + v]; qu[r] = qsh[r * cV + u]; }
        #pragma unroll
        for (int s = 0; s < 4; ++s) {
            float s1 = c1bs[s], s2 = c2bs[s];
            #pragma unroll
            for (int r = 0; r < 4; ++r) {
                s1 += c1sh[s * 4 + r] * (kv[r] * qu[r]);
                s2 += c2sh[s * 4 + r] * (kv[r] - qu[r]);
            }
            aarr[s]     = tanhf(s1);
            aarr[4 + s] = tanhf(s2);
        }
        float ad = adjsh[p];
        size_t base = (size_t)n * cO * (cV * cV) + p;
        #pragma unroll 8
        for (int o = 0; o < cO; ++o) {
            float acc = fbs[o];
            #pragma unroll
            for (int j = 0; j < 8; ++j) acc += fwsh[o * 8 + j] * aarr[j];
            g_att[base + (size_t)o * (cV * cV)] = al * acc + ad;
        }
    }
}

// ---------------------------------------------------------------------------
// K3: vten[n,o,i] = sum_c Wv[o,c] * x[n,c,i] + bv[o],  i in [0,3200)
// grid (25, N): 128-wide i-chunks. 128 threads: osub=tid>>4 (8), tug=tid&15,
// thread tile = 8 o (4 f32x2 pairs) x 8 i. smem: xs 32KB + wp 16KB -> 4 blk/SM.
// Warp = 2 osub x 16 tug: wp loads are 2-address (near-broadcast), xs loads
// 2x LDS.128. ~10 wavefronts per 16 FMA-issue-cycles -> FMA-bound.
// ---------------------------------------------------------------------------
constexpr int CH = 128;  // i-chunk

__global__ void __launch_bounds__(128, 4) k_vten(
    const float* __restrict__ x, const float* __restrict__ Wv,
    const float* __restrict__ bv) {
    extern __shared__ float sm[];
    float* xs  = sm;                    // [64][128]
    ull*   wp  = (ull*)(sm + cC * CH);  // [32 o-pairs][64 c]

    int n  = blockIdx.y;
    int i0 = blockIdx.x * CH;
    int tid = threadIdx.x;

    // stage x chunk: 64 rows of 128 floats (32 float4 each)
    for (int i = tid; i < cC * (CH / 4); i += 128) {
        int c = i >> 5, j = i & 31;
        ((float4*)xs)[i] =
            ((const float4*)(x + (size_t)(n * cC + c) * TV + i0))[j];
    }
    // stage duplicated o-pair weights
    for (int i = tid; i < 32 * cC; i += 128) {
        int pp = i >> 6, c = i & 63;
        ((float2*)wp)[i] = make_float2(Wv[(2 * pp) * cC + c],
                                       Wv[(2 * pp + 1) * cC + c]);
    }
    __syncthreads();

    int osub = tid >> 4;          // 0..7
    int tug  = tid & 15;          // 0..15
    int tu0  = tug * 8;
    const ull* wbase = wp + (osub * 4) * cC;

    ull acc[4][8];
    #pragma unroll
    for (int pp = 0; pp < 4; ++pp)
        #pragma unroll
        for (int j = 0; j < 8; ++j) acc[pp][j] = 0ull;

    #pragma unroll 4
    for (int c = 0; c < cC; ++c) {
        float4 xa = *(const float4*)(xs + c * CH + tu0);
        float4 xb = *(const float4*)(xs + c * CH + tu0 + 4);
        ull xd[8];
        asm("mov.b64 %0, {%1, %1};" : "=l"(xd[0]) : "f"(xa.x));
        asm("mov.b64 %0, {%1, %1};" : "=l"(xd[1]) : "f"(xa.y));
        asm("mov.b64 %0, {%1, %1};" : "=l"(xd[2]) : "f"(xa.z));
        asm("mov.b64 %0, {%1, %1};" : "=l"(xd[3]) : "f"(xa.w));
        asm("mov.b64 %0, {%1, %1};" : "=l"(xd[4]) : "f"(xb.x));
        asm("mov.b64 %0, {%1, %1};" : "=l"(xd[5]) : "f"(xb.y));
        asm("mov.b64 %0, {%1, %1};" : "=l"(xd[6]) : "f"(xb.z));
        asm("mov.b64 %0, {%1, %1};" : "=l"(xd[7]) : "f"(xb.w));
        #pragma unroll
        for (int pp = 0; pp < 4; ++pp) {
            ull w = wbase[pp * cC + c];
            #pragma unroll
            for (int j = 0; j < 8; ++j)
                asm("fma.rn.f32x2 %0, %1, %2, %0;"
                    : "+l"(acc[pp][j]) : "l"(xd[j]), "l"(w));
        }
    }

    // epilogue: add bias, store 8 o-rows x 8 i as 2 float4 each
    #pragma unroll
    for (int pp = 0; pp < 4; ++pp) {
        int olo = osub * 8 + 2 * pp;
        float blo = __ldg(bv + olo), bhi = __ldg(bv + olo + 1);
        float lo[8], hi[8];
        #pragma unroll
        for (int j = 0; j < 8; ++j)
            asm("mov.b64 {%0, %1}, %2;" : "=f"(lo[j]), "=f"(hi[j]) : "l"(acc[pp][j]));
        float* plo = g_vten + (size_t)(n * cO + olo) * TV + i0 + tu0;
        float* phi = plo + TV;
        ((float4*)plo)[0] = make_float4(lo[0]+blo, lo[1]+blo, lo[2]+blo, lo[3]+blo);
        ((float4*)plo)[1] = make_float4(lo[4]+blo, lo[5]+blo, lo[6]+blo, lo[7]+blo);
        ((float4*)phi)[0] = make_float4(hi[0]+bhi, hi[1]+bhi, hi[2]+bhi, hi[3]+bhi);
        ((float4*)phi)[1] = make_float4(hi[4]+bhi, hi[5]+bhi, hi[6]+bhi, hi[7]+bhi);
    }
}

// ---------------------------------------------------------------------------
// K4: out[n,o,t,v] = sum_u att[n,o,v,u] * vten[n,o,t,u]
// grid (32, N): o-pairs. 256 thr: oi=tid>>7, vg=(tid>>5)&3, tg=tid&31.
// Thread tile: 4 v-pairs (v = vg*8+2vp) x 4 t (t = ti*32+tg, interleaved).
// att rows broadcast (warp lanes differ only in tg), vt scalars conflict-free
// (stride 27). 6 wf per 8 FMA-cycles -> FMA side ok; kernel is DRAM-bound.
// ---------------------------------------------------------------------------
constexpr int VTS = 27;                    // vt row stride (odd, pad)
constexpr int ATS = 32;                    // attT row stride (v-padded)

__global__ void __launch_bounds__(256, 3) k_out(
    float* __restrict__ out) {
    __shared__ float vtr[2 * cT * VTS];        // 6912 fl, reused as outsh
    __shared__ float attsh[2 * cV * ATS];      // 1600 fl

    int n  = blockIdx.y;
    int op = blockIdx.x;                       // o-pair
    int tid = threadIdx.x;
    int obase = n * cO + op * 2;

    // stage vt (both o's), padded rows
    for (int i = tid; i < 2 * TV; i += 256) {
        int oi2 = i / TV, r = i - oi2 * TV;
        int t = r / cV, u = r - t * cV;
        vtr[oi2 * (cT * VTS) + t * VTS + u] =
            g_vten[(size_t)(obase + oi2) * TV + r];
    }
    // stage attT[oi][u][v] (transpose), then zero v-pad cols 25..31
    for (int i = tid; i < 2 * cV * cV; i += 256) {
        int oi2 = i / 625, r = i - oi2 * 625;
        int v = r / cV, u = r - v * cV;
        attsh[oi2 * (cV * ATS) + u * ATS + v] =
            g_att[(size_t)(obase + oi2) * 625 + r];
    }
    for (int i = tid; i < 2 * cV * 7; i += 256) {
        int oi2 = i / 175, r = i - oi2 * 175;
        int u = r / 7, v = cV + r - u * 7;
        attsh[oi2 * (cV * ATS) + u * ATS + v] = 0.f;
    }
    __syncthreads();

    int oi = tid >> 7;
    int vg = (tid >> 5) & 3;
    int tg = tid & 31;
    const float* vb = vtr + oi * (cT * VTS) + tg * VTS;   // + ti*32*VTS + u
    const float* ab = attsh + oi * (cV * ATS) + vg * 8;   // + u*ATS (+2vp)

    ull acc[4][4];    // [vp][ti]
    #pragma unroll
    for (int vp = 0; vp < 4; ++vp)
        #pragma unroll
        for (int ti = 0; ti < 4; ++ti) acc[vp][ti] = 0ull;

    #pragma unroll
    for (int u = 0; u < cV; ++u) {
        const ull* arow = (const ull*)(ab + u * ATS);     // 4 ull, 16B-aligned
        ull a0 = arow[0], a1 = arow[1], a2 = arow[2], a3 = arow[3];
        ull xd[4];
        #pragma unroll
        for (int ti = 0; ti < 4; ++ti) {
            float xv = vb[ti * (32 * VTS) + u];
            asm("mov.b64 %0, {%1, %1};" : "=l"(xd[ti]) : "f"(xv));
        }
        #pragma unroll
        for (int ti = 0; ti < 4; ++ti) {
            asm("fma.rn.f32x2 %0, %1, %2, %0;" : "+l"(acc[0][ti]) : "l"(a0), "l"(xd[ti]));
            asm("fma.rn.f32x2 %0, %1, %2, %0;" : "+l"(acc[1][ti]) : "l"(a1), "l"(xd[ti]));
            asm("fma.rn.f32x2 %0, %1, %2, %0;" : "+l"(acc[2][ti]) : "l"(a2), "l"(xd[ti]));
            asm("fma.rn.f32x2 %0, %1, %2, %0;" : "+l"(acc[3][ti]) : "l"(a3), "l"(xd[ti]));
        }
    }
    __syncthreads();   // done reading vtr -> safe to reuse as outsh [oi][t*26+v]

    float* outsh = vtr;
    #pragma unroll
    for (int ti = 0; ti < 4; ++ti) {
        int t = ti * 32 + tg;
        float* orow = outsh + oi * (cT * VTS) + t * 26;
        #pragma unroll
        for (int vp = 0; vp < 4; ++vp) {
            int v = vg * 8 + 2 * vp;
            if (v < 24) {
                *(ull*)(orow + v) = acc[vp][ti];
            } else if (v == 24) {
                float lo, hi;
                asm("mov.b64 {%0, %1}, %2;" : "=f"(lo), "=f"(hi) : "l"(acc[vp][ti]));
                orow[v] = lo;
            }
        }
    }
    __syncthreads();

    // coalesced writeback
    for (int i = tid; i < 2 * TV; i += 256) {
        int oi2 = i / TV, r = i - oi2 * TV;
        int t = r / cV, u = r - t * cV;
        out[(size_t)(obase + oi2) * TV + r] =
            outsh[oi2 * (cT * VTS) + t * 26 + u];
    }
}

// ---------------------------------------------------------------------------
extern "C" void kernel_launch(void* const* d_in, const int* in_sizes, int n_in,
                              void* d_out, int out_size) {
    const float* x    = (const float*)d_in[0];
    const float* adj  = (const float*)d_in[1];
    const float* Wk   = (const float*)d_in[2];
    const float* bk   = (const float*)d_in[3];
    const float* Wq   = (const float*)d_in[4];
    const float* bq   = (const float*)d_in[5];
    const float* Wv   = (const float*)d_in[6];
    const float* bv   = (const float*)d_in[7];
    const float* c1w  = (const float*)d_in[8];
    const float* c1b  = (const float*)d_in[9];
    const float* c2w  = (const float*)d_in[10];
    const float* c2b  = (const float*)d_in[11];
    const float* fw   = (const float*)d_in[12];
    const float* fb   = (const float*)d_in[13];
    const float* alpha= (const float*)d_in[14];
    float* out = (float*)d_out;

    int vten_smem = (cC * CH + 32 * cC * 2) * (int)sizeof(float);  // 49152
    cudaFuncSetAttribute((const void*)k_vten,
                         cudaFuncAttributeMaxDynamicSharedMemorySize, vten_smem);

    k_sum_t<<<dim3(8, cN), 256>>>(x);
    k_att_kernel<<<cN, 256>>>(adj, Wk, bk, Wq, bq, c1w, c1b, c2w, c2b, fw, fb, alpha);
    k_vten<<<dim3(TV / CH, cN), 128, vten_smem>>>(x, Wv, bv);
    k_out<<<dim3(cO / 2, cN), 256>>>(out);
}